// round 7
// baseline (speedup 1.0000x reference)
#include <cuda_runtime.h>
#include <cstdint>

// Shapes (fixed by the problem)
#define TT 1024   // tokens
#define HH 2048   // hidden
#define II 1024   // intermediate
#define EE 32     // experts
// GEMM tiling: CTA tile 64(M) x 128(N), 4 warps, warp tile 64x32
#define BM 64
#define BN 128
#define BK 32
#define RT 4      // tokens per router block

// ---------------- device scratch (static: no allocations allowed) ----------
__device__ int   g_cnt[EE];
__device__ int   g_tok [EE][TT];
__device__ float g_wt  [EE][TT];
__device__ int   g_prow[EE][TT];
__device__ float g_x[TT][HH];       // tf32-rounded activations: 8 MB
__device__ float g_u[TT * 2][II];   // raw up-proj outputs per pair row: 8 MB
__device__ float g_h[TT * 2][II];   // tf32-rounded silu(g)*u*wt per pair: 8 MB
__device__ float g_o[TT * 2][HH];   // per-pair down_proj partials: 16 MB

// ---------------- helpers ---------------------------------------------------
__device__ __forceinline__ uint32_t tf32r(float v) {
    uint32_t r;
    asm("cvt.rna.tf32.f32 %0, %1;" : "=r"(r) : "f"(v));
    return r;
}

__device__ __forceinline__ void mma_tf32(float* d, const uint32_t* a,
                                         uint32_t b0, uint32_t b1) {
    asm volatile(
        "mma.sync.aligned.m16n8k8.row.col.f32.tf32.tf32.f32 "
        "{%0,%1,%2,%3}, {%4,%5,%6,%7}, {%8,%9}, {%0,%1,%2,%3};\n"
        : "+f"(d[0]), "+f"(d[1]), "+f"(d[2]), "+f"(d[3])
        : "r"(a[0]), "r"(a[1]), "r"(a[2]), "r"(a[3]), "r"(b0), "r"(b1));
}

// 16B cp.async with zero-fill predicate (CUTLASS zfill form)
__device__ __forceinline__ void cp16(void* smem, const void* gmem, bool pred) {
    uint32_t sa = (uint32_t)__cvta_generic_to_shared(smem);
    int sz = pred ? 16 : 0;
    asm volatile("cp.async.cg.shared.global [%0], [%1], 16, %2;\n"
                 :: "r"(sa), "l"(gmem), "r"(sz));
}
__device__ __forceinline__ void cp_commit() {
    asm volatile("cp.async.commit_group;\n");
}

// ---------------- kernel 0: zero counters -----------------------------------
__global__ void zero_cnt_kernel() {
    if (threadIdx.x < EE) g_cnt[threadIdx.x] = 0;
}

// ---------------- kernel 1: router + tf32 pre-round of x ---------------------
__global__ __launch_bounds__(128)
void router_kernel(const float* __restrict__ x, const float* __restrict__ gw) {
    __shared__ float xs[RT][HH];     // 32 KB
    __shared__ float lg[RT][EE];

    const int t0 = blockIdx.x * RT;
    for (int i = threadIdx.x; i < RT * (HH / 4); i += 128) {
        const int rt = i >> 9;             // HH/4 = 512
        const int c  = i & 511;
        reinterpret_cast<float4*>(xs[rt])[c] =
            reinterpret_cast<const float4*>(x + (size_t)(t0 + rt) * HH)[c];
    }
    __syncthreads();

    // tf32-rounded copy of x for the GEMMs (removes cvt from GEMM A path)
    {
        const float* xf = &xs[0][0];
        float* gx = &g_x[t0][0];
        for (int i = threadIdx.x * 4; i < RT * HH; i += 128 * 4) {
            float4 v = *reinterpret_cast<const float4*>(xf + i);
            v.x = __uint_as_float(tf32r(v.x));
            v.y = __uint_as_float(tf32r(v.y));
            v.z = __uint_as_float(tf32r(v.z));
            v.w = __uint_as_float(tf32r(v.w));
            *reinterpret_cast<float4*>(gx + i) = v;
        }
    }

    const int warp = threadIdx.x >> 5, lane = threadIdx.x & 31;
    const float4* xv = reinterpret_cast<const float4*>(xs[warp]);
    for (int e = 0; e < EE; e++) {
        const float4* wv = reinterpret_cast<const float4*>(gw + (size_t)e * HH);
        float acc = 0.f;
        for (int k = lane; k < HH / 4; k += 32) {
            float4 a = xv[k], b = wv[k];
            acc += a.x * b.x + a.y * b.y + a.z * b.z + a.w * b.w;
        }
        #pragma unroll
        for (int o = 16; o; o >>= 1) acc += __shfl_xor_sync(0xffffffffu, acc, o);
        if (lane == 0) lg[warp][e] = acc;
    }
    if (lane == 0) {
        const int t = t0 + warp;
        float v0 = -1e30f, v1 = -1e30f; int i0 = 0, i1 = 0;
        for (int e = 0; e < EE; e++) {
            const float v = lg[warp][e];
            if (v > v0)      { v1 = v0; i1 = i0; v0 = v; i0 = e; }
            else if (v > v1) { v1 = v;  i1 = e; }
        }
        const float w0 = 1.f / (1.f + expf(v1 - v0));
        const float w1 = 1.f - w0;
        int s0 = atomicAdd(&g_cnt[i0], 1);
        g_tok[i0][s0] = t; g_wt[i0][s0] = w0; g_prow[i0][s0] = 2 * t;
        int s1 = atomicAdd(&g_cnt[i1], 1);
        g_tok[i1][s1] = t; g_wt[i1][s1] = w1; g_prow[i1][s1] = 2 * t + 1;
    }
}

// ============ shared GEMM structure ==========================================
// smem/stage: A 64x32 (8KB) + B 128x32 (16KB); 2 stages = 48 KB static.
// XOR swizzle: 16B chunk c of row r stored at chunk c ^ (r & 7).
// Fragment loads: all rows/cols have (idx & 7) == grp -> swizzle = ^grp.

// ---------------- kernel 2a: up-proj GEMM -> g_u -----------------------------
// grid = (II/BN = 8, EE * 16)
__global__ __launch_bounds__(128, 4)
void moe_up_kernel(const float* __restrict__ wu) {
    const int e  = blockIdx.y >> 4;
    const int mt = blockIdx.y & 15;
    const int ne = g_cnt[e];
    if (mt * BM >= ne) return;
    const int nt = blockIdx.x;

    __shared__ float As[2][BM][BK];
    __shared__ float Bs[2][BN][BK];

    const int tid = threadIdx.x;
    const int lr = tid >> 3;
    const int cw = tid & 7;

    int tok[4];
    #pragma unroll
    for (int j = 0; j < 4; j++) {
        const int slot = mt * BM + lr + j * 16;
        tok[j] = (slot < ne) ? g_tok[e][slot] : -1;
    }

    const float* wE = wu + ((size_t)e * II + (size_t)nt * BN) * HH;

    auto load_stage = [&](int k0, int buf) {
        #pragma unroll
        for (int j = 0; j < 4; j++) {
            const int r  = lr + j * 16;
            const int sc = ((cw ^ (r & 7)) << 2);
            const int ta = (tok[j] < 0) ? 0 : tok[j];
            cp16(&As[buf][r][sc], &g_x[ta][k0 + (cw << 2)], tok[j] >= 0);
        }
        #pragma unroll
        for (int j = 0; j < 8; j++) {
            const int r  = lr + j * 16;
            const int sc = ((cw ^ (r & 7)) << 2);
            cp16(&Bs[buf][r][sc], wE + (size_t)r * HH + k0 + (cw << 2), true);
        }
    };

    const int warp = tid >> 5, lane = tid & 31;
    const int wn = warp * 32;
    const int grp = lane >> 2, tg = lane & 3;

    float acc[4][4][4];
    #pragma unroll
    for (int a = 0; a < 4; a++)
        #pragma unroll
        for (int b = 0; b < 4; b++)
            #pragma unroll
            for (int c = 0; c < 4; c++) acc[a][b][c] = 0.f;

    load_stage(0, 0); cp_commit();

    const int NK = HH / BK;   // 64
    for (int kt = 0; kt < NK; kt++) {
        const int buf = kt & 1;
        if (kt + 1 < NK) {
            load_stage((kt + 1) * BK, buf ^ 1); cp_commit();
            asm volatile("cp.async.wait_group 1;\n");
        } else {
            asm volatile("cp.async.wait_group 0;\n");
        }
        __syncthreads();

        #pragma unroll
        for (int kk = 0; kk < BK; kk += 8) {
            const int c0 = (((kk >> 2)    ) ^ grp) << 2;
            const int c1 = (((kk >> 2) + 1) ^ grp) << 2;
            uint32_t a[4][4];
            #pragma unroll
            for (int mi = 0; mi < 4; mi++) {
                const int r0 = mi * 16 + grp, r1 = r0 + 8;
                a[mi][0] = __float_as_uint(As[buf][r0][c0 + tg]);
                a[mi][1] = __float_as_uint(As[buf][r1][c0 + tg]);
                a[mi][2] = __float_as_uint(As[buf][r0][c1 + tg]);
                a[mi][3] = __float_as_uint(As[buf][r1][c1 + tg]);
            }
            #pragma unroll
            for (int ni = 0; ni < 4; ni++) {
                const int col = wn + ni * 8 + grp;
                const uint32_t b0 = tf32r(Bs[buf][col][c0 + tg]);
                const uint32_t b1 = tf32r(Bs[buf][col][c1 + tg]);
                #pragma unroll
                for (int mi = 0; mi < 4; mi++)
                    mma_tf32(acc[mi][ni], a[mi], b0, b1);
            }
        }
        __syncthreads();
    }

    // epilogue: store raw u per pair row
    #pragma unroll
    for (int mi = 0; mi < 4; mi++) {
        #pragma unroll
        for (int h2 = 0; h2 < 2; h2++) {
            const int rloc = mi * 16 + grp + h2 * 8;
            const int slot = mt * BM + rloc;
            if (slot >= ne) continue;
            float* urow = g_u[g_prow[e][slot]];
            #pragma unroll
            for (int ni = 0; ni < 4; ni++) {
                *reinterpret_cast<float2*>(urow + nt * BN + wn + ni * 8 + tg * 2) =
                    make_float2(acc[mi][ni][h2 * 2 + 0], acc[mi][ni][h2 * 2 + 1]);
            }
        }
    }
}

// ---------------- kernel 2b: gate-proj GEMM + SwiGLU -> g_h ------------------
// grid = (II/BN = 8, EE * 16)
__global__ __launch_bounds__(128, 4)
void moe_gate_kernel(const float* __restrict__ wg) {
    const int e  = blockIdx.y >> 4;
    const int mt = blockIdx.y & 15;
    const int ne = g_cnt[e];
    if (mt * BM >= ne) return;
    const int nt = blockIdx.x;

    __shared__ float As[2][BM][BK];
    __shared__ float Bs[2][BN][BK];

    const int tid = threadIdx.x;
    const int lr = tid >> 3;
    const int cw = tid & 7;

    int tok[4];
    #pragma unroll
    for (int j = 0; j < 4; j++) {
        const int slot = mt * BM + lr + j * 16;
        tok[j] = (slot < ne) ? g_tok[e][slot] : -1;
    }

    const float* wE = wg + ((size_t)e * II + (size_t)nt * BN) * HH;

    auto load_stage = [&](int k0, int buf) {
        #pragma unroll
        for (int j = 0; j < 4; j++) {
            const int r  = lr + j * 16;
            const int sc = ((cw ^ (r & 7)) << 2);
            const int ta = (tok[j] < 0) ? 0 : tok[j];
            cp16(&As[buf][r][sc], &g_x[ta][k0 + (cw << 2)], tok[j] >= 0);
        }
        #pragma unroll
        for (int j = 0; j < 8; j++) {
            const int r  = lr + j * 16;
            const int sc = ((cw ^ (r & 7)) << 2);
            cp16(&Bs[buf][r][sc], wE + (size_t)r * HH + k0 + (cw << 2), true);
        }
    };

    const int warp = tid >> 5, lane = tid & 31;
    const int wn = warp * 32;
    const int grp = lane >> 2, tg = lane & 3;

    float acc[4][4][4];
    #pragma unroll
    for (int a = 0; a < 4; a++)
        #pragma unroll
        for (int b = 0; b < 4; b++)
            #pragma unroll
            for (int c = 0; c < 4; c++) acc[a][b][c] = 0.f;

    load_stage(0, 0); cp_commit();

    const int NK = HH / BK;   // 64
    for (int kt = 0; kt < NK; kt++) {
        const int buf = kt & 1;
        if (kt + 1 < NK) {
            load_stage((kt + 1) * BK, buf ^ 1); cp_commit();
            asm volatile("cp.async.wait_group 1;\n");
        } else {
            asm volatile("cp.async.wait_group 0;\n");
        }
        __syncthreads();

        #pragma unroll
        for (int kk = 0; kk < BK; kk += 8) {
            const int c0 = (((kk >> 2)    ) ^ grp) << 2;
            const int c1 = (((kk >> 2) + 1) ^ grp) << 2;
            uint32_t a[4][4];
            #pragma unroll
            for (int mi = 0; mi < 4; mi++) {
                const int r0 = mi * 16 + grp, r1 = r0 + 8;
                a[mi][0] = __float_as_uint(As[buf][r0][c0 + tg]);
                a[mi][1] = __float_as_uint(As[buf][r1][c0 + tg]);
                a[mi][2] = __float_as_uint(As[buf][r0][c1 + tg]);
                a[mi][3] = __float_as_uint(As[buf][r1][c1 + tg]);
            }
            #pragma unroll
            for (int ni = 0; ni < 4; ni++) {
                const int col = wn + ni * 8 + grp;
                const uint32_t b0 = tf32r(Bs[buf][col][c0 + tg]);
                const uint32_t b1 = tf32r(Bs[buf][col][c1 + tg]);
                #pragma unroll
                for (int mi = 0; mi < 4; mi++)
                    mma_tf32(acc[mi][ni], a[mi], b0, b1);
            }
        }
        __syncthreads();
    }

    // epilogue: h = silu(g) * u * wt, tf32-rounded -> g_h
    #pragma unroll
    for (int mi = 0; mi < 4; mi++) {
        #pragma unroll
        for (int h2 = 0; h2 < 2; h2++) {
            const int rloc = mi * 16 + grp + h2 * 8;
            const int slot = mt * BM + rloc;
            if (slot >= ne) continue;
            const float wt = g_wt[e][slot];
            const int prow = g_prow[e][slot];
            float* hrow = g_h[prow];
            const float* urow = g_u[prow];
            #pragma unroll
            for (int ni = 0; ni < 4; ni++) {
                const int col = nt * BN + wn + ni * 8 + tg * 2;
                const float2 u2 = *reinterpret_cast<const float2*>(urow + col);
                const float gg0 = acc[mi][ni][h2 * 2 + 0];
                const float gg1 = acc[mi][ni][h2 * 2 + 1];
                const float h0 = gg0 / (1.f + __expf(-gg0)) * u2.x * wt;
                const float h1 = gg1 / (1.f + __expf(-gg1)) * u2.y * wt;
                *reinterpret_cast<float2*>(hrow + col) =
                    make_float2(__uint_as_float(tf32r(h0)),
                                __uint_as_float(tf32r(h1)));
            }
        }
    }
}

// ---------------- kernel 3: down_proj GEMM -> per-pair partials --------------
// grid = (HH/BN = 16, EE * 16)
__global__ __launch_bounds__(128, 4)
void moe_g2_kernel(const float* __restrict__ wd) {
    const int e  = blockIdx.y >> 4;
    const int mt = blockIdx.y & 15;
    const int ne = g_cnt[e];
    if (mt * BM >= ne) return;
    const int nt = blockIdx.x;

    __shared__ float As[2][BM][BK];
    __shared__ float Bs[2][BN][BK];

    const int tid = threadIdx.x;
    const int lr = tid >> 3;
    const int cw = tid & 7;

    int pr[4];
    #pragma unroll
    for (int j = 0; j < 4; j++) {
        const int slot = mt * BM + lr + j * 16;
        pr[j] = (slot < ne) ? g_prow[e][slot] : -1;
    }

    const float* wE = wd + ((size_t)e * HH + (size_t)nt * BN) * II;

    auto load_stage = [&](int k0, int buf) {
        #pragma unroll
        for (int j = 0; j < 4; j++) {
            const int r  = lr + j * 16;
            const int sc = ((cw ^ (r & 7)) << 2);
            const int pa = (pr[j] < 0) ? 0 : pr[j];
            cp16(&As[buf][r][sc], &g_h[pa][k0 + (cw << 2)], pr[j] >= 0);
        }
        #pragma unroll
        for (int j = 0; j < 8; j++) {
            const int r  = lr + j * 16;
            const int sc = ((cw ^ (r & 7)) << 2);
            cp16(&Bs[buf][r][sc], wE + (size_t)r * II + k0 + (cw << 2), true);
        }
    };

    const int warp = tid >> 5, lane = tid & 31;
    const int wn = warp * 32;
    const int grp = lane >> 2, tg = lane & 3;

    float acc[4][4][4];
    #pragma unroll
    for (int a = 0; a < 4; a++)
        #pragma unroll
        for (int b = 0; b < 4; b++)
            #pragma unroll
            for (int c = 0; c < 4; c++) acc[a][b][c] = 0.f;

    load_stage(0, 0); cp_commit();

    const int NK = II / BK;   // 32
    for (int kt = 0; kt < NK; kt++) {
        const int buf = kt & 1;
        if (kt + 1 < NK) {
            load_stage((kt + 1) * BK, buf ^ 1); cp_commit();
            asm volatile("cp.async.wait_group 1;\n");
        } else {
            asm volatile("cp.async.wait_group 0;\n");
        }
        __syncthreads();

        #pragma unroll
        for (int kk = 0; kk < BK; kk += 8) {
            const int c0 = (((kk >> 2)    ) ^ grp) << 2;
            const int c1 = (((kk >> 2) + 1) ^ grp) << 2;
            uint32_t a[4][4];
            #pragma unroll
            for (int mi = 0; mi < 4; mi++) {
                const int r0 = mi * 16 + grp, r1 = r0 + 8;
                a[mi][0] = __float_as_uint(As[buf][r0][c0 + tg]);
                a[mi][1] = __float_as_uint(As[buf][r1][c0 + tg]);
                a[mi][2] = __float_as_uint(As[buf][r0][c1 + tg]);
                a[mi][3] = __float_as_uint(As[buf][r1][c1 + tg]);
            }
            #pragma unroll
            for (int ni = 0; ni < 4; ni++) {
                const int col = wn + ni * 8 + grp;
                const uint32_t b0 = tf32r(Bs[buf][col][c0 + tg]);
                const uint32_t b1 = tf32r(Bs[buf][col][c1 + tg]);
                #pragma unroll
                for (int mi = 0; mi < 4; mi++)
                    mma_tf32(acc[mi][ni], a[mi], b0, b1);
            }
        }
        __syncthreads();
    }

    // epilogue: per-pair partial rows (deterministic, no atomics)
    #pragma unroll
    for (int mi = 0; mi < 4; mi++) {
        #pragma unroll
        for (int h2 = 0; h2 < 2; h2++) {
            const int rloc = mi * 16 + grp + h2 * 8;
            const int slot = mt * BM + rloc;
            if (slot >= ne) continue;
            float* orow = g_o[g_prow[e][slot]];
            #pragma unroll
            for (int ni = 0; ni < 4; ni++) {
                *reinterpret_cast<float2*>(orow + nt * BN + wn + ni * 8 + tg * 2) =
                    make_float2(acc[mi][ni][h2 * 2 + 0], acc[mi][ni][h2 * 2 + 1]);
            }
        }
    }
}

// ---------------- kernel 4: combine the two pairs of each token --------------
__global__ __launch_bounds__(256)
void combine_kernel(float* __restrict__ out) {
    const int i = blockIdx.x * 256 + threadIdx.x;   // over TT*HH/4 float4s
    const int t = i >> 9;                           // HH/4 = 512
    const int c = i & 511;
    const float4 a = reinterpret_cast<const float4*>(&g_o[2 * t][0])[c];
    const float4 b = reinterpret_cast<const float4*>(&g_o[2 * t + 1][0])[c];
    reinterpret_cast<float4*>(out)[i] =
        make_float4(a.x + b.x, a.y + b.y, a.z + b.z, a.w + b.w);
}

// ---------------- launch -----------------------------------------------------
extern "C" void kernel_launch(void* const* d_in, const int* in_sizes, int n_in,
                              void* d_out, int out_size) {
    const float* x  = (const float*)d_in[0];   // [T, H]
    const float* gw = (const float*)d_in[1];   // [E, H] router
    const float* wg = (const float*)d_in[2];   // [E, I, H] gate_proj
    const float* wu = (const float*)d_in[3];   // [E, I, H] up_proj
    const float* wd = (const float*)d_in[4];   // [E, H, I] down_proj
    float* out = (float*)d_out;                // [T, H]

    zero_cnt_kernel<<<1, 32>>>();
    router_kernel<<<TT / RT, 128>>>(x, gw);
    moe_up_kernel<<<dim3(II / BN, EE * 16), 128>>>(wu);
    moe_gate_kernel<<<dim3(II / BN, EE * 16), 128>>>(wg);
    moe_g2_kernel<<<dim3(HH / BN, EE * 16), 128>>>(wd);
    combine_kernel<<<(TT * HH / 4) / 256, 256>>>(out);
}

// round 9
// speedup vs baseline: 1.1839x; 1.1839x over previous
#include <cuda_runtime.h>
#include <cstdint>

// Shapes (fixed by the problem)
#define TT 1024   // tokens
#define HH 2048   // hidden
#define II 1024   // intermediate
#define EE 32     // experts
// GEMM tiling
#define BM 64
#define BN1 64    // g1 CTA N-tile (gate & up each)
#define BN2 128   // g2 CTA N-tile
#define BK 32
#define RT 4      // tokens per router block

// ---------------- device scratch (static: no allocations allowed) ----------
__device__ int   g_cnt[EE];
__device__ int   g_tok [EE][TT];
__device__ float g_wt  [EE][TT];
__device__ int   g_prow[EE][TT];
__device__ float g_x[TT][HH];       // tf32-rounded activations: 8 MB
__device__ float g_h[TT * 2][II];   // tf32-rounded silu(g)*u*wt per pair: 8 MB
__device__ float g_o[TT * 2][HH];   // per-pair down_proj partials: 16 MB

// ---------------- helpers ---------------------------------------------------
__device__ __forceinline__ uint32_t tf32r(float v) {
    uint32_t r;
    asm("cvt.rna.tf32.f32 %0, %1;" : "=r"(r) : "f"(v));
    return r;
}

__device__ __forceinline__ void mma_tf32(float* d, const uint32_t* a,
                                         uint32_t b0, uint32_t b1) {
    asm volatile(
        "mma.sync.aligned.m16n8k8.row.col.f32.tf32.tf32.f32 "
        "{%0,%1,%2,%3}, {%4,%5,%6,%7}, {%8,%9}, {%0,%1,%2,%3};\n"
        : "+f"(d[0]), "+f"(d[1]), "+f"(d[2]), "+f"(d[3])
        : "r"(a[0]), "r"(a[1]), "r"(a[2]), "r"(a[3]), "r"(b0), "r"(b1));
}

// 16B cp.async with zero-fill predicate (CUTLASS zfill form)
__device__ __forceinline__ void cp16(void* smem, const void* gmem, bool pred) {
    uint32_t sa = (uint32_t)__cvta_generic_to_shared(smem);
    int sz = pred ? 16 : 0;
    asm volatile("cp.async.cg.shared.global [%0], [%1], 16, %2;\n"
                 :: "r"(sa), "l"(gmem), "r"(sz));
}
__device__ __forceinline__ void cp_commit() {
    asm volatile("cp.async.commit_group;\n");
}

// ---------------- kernel 0: zero counters -----------------------------------
__global__ void zero_cnt_kernel() {
    if (threadIdx.x < EE) g_cnt[threadIdx.x] = 0;
}

// ---------------- kernel 1: router + tf32 pre-round of x ---------------------
__global__ __launch_bounds__(128)
void router_kernel(const float* __restrict__ x, const float* __restrict__ gw) {
    __shared__ float xs[RT][HH];     // 32 KB
    __shared__ float lg[RT][EE];

    const int t0 = blockIdx.x * RT;
    for (int i = threadIdx.x; i < RT * (HH / 4); i += 128) {
        const int rt = i >> 9;             // HH/4 = 512
        const int c  = i & 511;
        reinterpret_cast<float4*>(xs[rt])[c] =
            reinterpret_cast<const float4*>(x + (size_t)(t0 + rt) * HH)[c];
    }
    __syncthreads();

    // tf32-rounded copy of x for the GEMMs (removes cvt from GEMM A path)
    {
        const float* xf = &xs[0][0];
        float* gx = &g_x[t0][0];
        for (int i = threadIdx.x * 4; i < RT * HH; i += 128 * 4) {
            float4 v = *reinterpret_cast<const float4*>(xf + i);
            v.x = __uint_as_float(tf32r(v.x));
            v.y = __uint_as_float(tf32r(v.y));
            v.z = __uint_as_float(tf32r(v.z));
            v.w = __uint_as_float(tf32r(v.w));
            *reinterpret_cast<float4*>(gx + i) = v;
        }
    }

    const int warp = threadIdx.x >> 5, lane = threadIdx.x & 31;
    const float4* xv = reinterpret_cast<const float4*>(xs[warp]);
    for (int e = 0; e < EE; e++) {
        const float4* wv = reinterpret_cast<const float4*>(gw + (size_t)e * HH);
        float acc = 0.f;
        for (int k = lane; k < HH / 4; k += 32) {
            float4 a = xv[k], b = wv[k];
            acc += a.x * b.x + a.y * b.y + a.z * b.z + a.w * b.w;
        }
        #pragma unroll
        for (int o = 16; o; o >>= 1) acc += __shfl_xor_sync(0xffffffffu, acc, o);
        if (lane == 0) lg[warp][e] = acc;
    }
    if (lane == 0) {
        const int t = t0 + warp;
        float v0 = -1e30f, v1 = -1e30f; int i0 = 0, i1 = 0;
        for (int e = 0; e < EE; e++) {
            const float v = lg[warp][e];
            if (v > v0)      { v1 = v0; i1 = i0; v0 = v; i0 = e; }
            else if (v > v1) { v1 = v;  i1 = e; }
        }
        const float w0 = 1.f / (1.f + expf(v1 - v0));
        const float w1 = 1.f - w0;
        int s0 = atomicAdd(&g_cnt[i0], 1);
        g_tok[i0][s0] = t; g_wt[i0][s0] = w0; g_prow[i0][s0] = 2 * t;
        int s1 = atomicAdd(&g_cnt[i1], 1);
        g_tok[i1][s1] = t; g_wt[i1][s1] = w1; g_prow[i1][s1] = 2 * t + 1;
    }
}

// ---------------- kernel 2: fused gate&up GEMM + SwiGLU ----------------------
// grid = (II/BN1 = 16, EE * 16); CTA = 128 thr = 4 warps.
// CTA tile 64(M) x 64(N); warps 0-1 compute gate, warps 2-3 compute up,
// each with warp tile 64(M) x 32(N) on a single B matrix (1.5 ops/mma).
// smem: 2 stages x 3 tiles x 64x32 fp32 = 48 KB.
// Epilogue: up warps exchange u via smem (reusing As), gate warps do SwiGLU.
__global__ __launch_bounds__(128, 4)
void moe_g1_kernel(const float* __restrict__ wg,
                   const float* __restrict__ wu) {
    const int e  = blockIdx.y >> 4;
    const int mt = blockIdx.y & 15;
    const int ne = g_cnt[e];
    if (mt * BM >= ne) return;
    const int nt = blockIdx.x;

    __shared__ float As[2][BM][BK];
    __shared__ float Bg[2][BN1][BK];
    __shared__ float Bu[2][BN1][BK];

    const int tid = threadIdx.x;
    const int lr = tid >> 3;       // load row base (0..15)
    const int cw = tid & 7;        // 16B chunk (0..7)

    int tok[4];
    #pragma unroll
    for (int j = 0; j < 4; j++) {
        const int slot = mt * BM + lr + j * 16;
        tok[j] = (slot < ne) ? g_tok[e][slot] : -1;
    }

    const float* wgE = wg + ((size_t)e * II + (size_t)nt * BN1) * HH;
    const float* wuE = wu + ((size_t)e * II + (size_t)nt * BN1) * HH;

    auto load_stage = [&](int k0, int buf) {
        #pragma unroll
        for (int j = 0; j < 4; j++) {
            const int r  = lr + j * 16;
            const int sc = ((cw ^ (r & 7)) << 2);
            const int ta = (tok[j] < 0) ? 0 : tok[j];
            cp16(&As[buf][r][sc], &g_x[ta][k0 + (cw << 2)], tok[j] >= 0);
            cp16(&Bg[buf][r][sc], wgE + (size_t)r * HH + k0 + (cw << 2), true);
            cp16(&Bu[buf][r][sc], wuE + (size_t)r * HH + k0 + (cw << 2), true);
        }
    };

    const int warp = tid >> 5, lane = tid & 31;
    const bool isGate = (warp < 2);
    const int wn = (warp & 1) * 32;            // N offset within 64-wide tile
    const int grp = lane >> 2, tg = lane & 3;

    float acc[4][4][4];
    #pragma unroll
    for (int a = 0; a < 4; a++)
        #pragma unroll
        for (int b = 0; b < 4; b++)
            #pragma unroll
            for (int c = 0; c < 4; c++) acc[a][b][c] = 0.f;

    load_stage(0, 0); cp_commit();

    const int NK = HH / BK;   // 64
    for (int kt = 0; kt < NK; kt++) {
        const int buf = kt & 1;
        if (kt + 1 < NK) {
            load_stage((kt + 1) * BK, buf ^ 1); cp_commit();
            asm volatile("cp.async.wait_group 1;\n");
        } else {
            asm volatile("cp.async.wait_group 0;\n");
        }
        __syncthreads();

        const float* Bp = isGate ? &Bg[buf][0][0] : &Bu[buf][0][0];

        #pragma unroll
        for (int kk = 0; kk < BK; kk += 8) {
            // fragment rows/cols all have (idx & 7) == grp -> swizzle = ^grp
            const int c0 = (((kk >> 2)    ) ^ grp) << 2;
            const int c1 = (((kk >> 2) + 1) ^ grp) << 2;
            uint32_t a[4][4];
            #pragma unroll
            for (int mi = 0; mi < 4; mi++) {
                const int r0 = mi * 16 + grp, r1 = r0 + 8;
                a[mi][0] = __float_as_uint(As[buf][r0][c0 + tg]);
                a[mi][1] = __float_as_uint(As[buf][r1][c0 + tg]);
                a[mi][2] = __float_as_uint(As[buf][r0][c1 + tg]);
                a[mi][3] = __float_as_uint(As[buf][r1][c1 + tg]);
            }
            #pragma unroll
            for (int ni = 0; ni < 4; ni++) {
                const int col = wn + ni * 8 + grp;
                const uint32_t b0 = tf32r(Bp[col * BK + c0 + tg]);
                const uint32_t b1 = tf32r(Bp[col * BK + c1 + tg]);
                #pragma unroll
                for (int mi = 0; mi < 4; mi++)
                    mma_tf32(acc[mi][ni], a[mi], b0, b1);
            }
        }
        __syncthreads();
    }

    // -------- epilogue: exchange u via smem, gate warps do SwiGLU ------------
    // As (2*64*32 = 4096 floats) is dead; reuse as uex[64][64].
    float (*uex)[BN1] = reinterpret_cast<float(*)[BN1]>(&As[0][0][0]);

    if (!isGate) {
        #pragma unroll
        for (int mi = 0; mi < 4; mi++) {
            #pragma unroll
            for (int h2 = 0; h2 < 2; h2++) {
                const int row = mi * 16 + grp + h2 * 8;
                #pragma unroll
                for (int ni = 0; ni < 4; ni++) {
                    const int col = wn + ni * 8 + tg * 2;
                    uex[row][col    ] = acc[mi][ni][h2 * 2 + 0];
                    uex[row][col + 1] = acc[mi][ni][h2 * 2 + 1];
                }
            }
        }
    }
    __syncthreads();
    if (isGate) {
        #pragma unroll
        for (int mi = 0; mi < 4; mi++) {
            #pragma unroll
            for (int h2 = 0; h2 < 2; h2++) {
                const int rloc = mi * 16 + grp + h2 * 8;
                const int slot = mt * BM + rloc;
                if (slot >= ne) continue;
                const float wt = g_wt[e][slot];
                float* hrow = g_h[g_prow[e][slot]];
                #pragma unroll
                for (int ni = 0; ni < 4; ni++) {
                    const int col = wn + ni * 8 + tg * 2;
                    const float u0 = uex[rloc][col];
                    const float u1 = uex[rloc][col + 1];
                    const float gg0 = acc[mi][ni][h2 * 2 + 0];
                    const float gg1 = acc[mi][ni][h2 * 2 + 1];
                    const float h0 = gg0 / (1.f + __expf(-gg0)) * u0 * wt;
                    const float h1 = gg1 / (1.f + __expf(-gg1)) * u1 * wt;
                    *reinterpret_cast<float2*>(hrow + nt * BN1 + col) =
                        make_float2(__uint_as_float(tf32r(h0)),
                                    __uint_as_float(tf32r(h1)));
                }
            }
        }
    }
}

// ---------------- kernel 3: down_proj GEMM -> per-pair partials --------------
// grid = (HH/BN2 = 16, EE * 16); CTA tile 64x128, warp tile 32x64 (2x2 warps)
// smem: 2 x (64x32 + 128x32) fp32 = 48 KB.  A (g_h) pre-rounded -> no cvt.
__global__ __launch_bounds__(128, 4)
void moe_g2_kernel(const float* __restrict__ wd) {
    const int e  = blockIdx.y >> 4;
    const int mt = blockIdx.y & 15;
    const int ne = g_cnt[e];
    if (mt * BM >= ne) return;
    const int nt = blockIdx.x;

    __shared__ float As[2][BM][BK];
    __shared__ float Bs[2][BN2][BK];

    const int tid = threadIdx.x;
    const int lr = tid >> 3;
    const int cw = tid & 7;

    int pr[4];
    #pragma unroll
    for (int j = 0; j < 4; j++) {
        const int slot = mt * BM + lr + j * 16;
        pr[j] = (slot < ne) ? g_prow[e][slot] : -1;
    }

    const float* wdE = wd + ((size_t)e * HH + (size_t)nt * BN2) * II;

    auto load_stage = [&](int k0, int buf) {
        #pragma unroll
        for (int j = 0; j < 4; j++) {
            const int r  = lr + j * 16;
            const int sc = ((cw ^ (r & 7)) << 2);
            const int pa = (pr[j] < 0) ? 0 : pr[j];
            cp16(&As[buf][r][sc], &g_h[pa][k0 + (cw << 2)], pr[j] >= 0);
        }
        #pragma unroll
        for (int j = 0; j < 8; j++) {
            const int r  = lr + j * 16;
            const int sc = ((cw ^ (r & 7)) << 2);
            cp16(&Bs[buf][r][sc], wdE + (size_t)r * II + k0 + (cw << 2), true);
        }
    };

    const int warp = tid >> 5, lane = tid & 31;
    const int wm = (warp >> 1) * 32, wn = (warp & 1) * 64;
    const int grp = lane >> 2, tg = lane & 3;

    float acc[2][8][4];
    #pragma unroll
    for (int a = 0; a < 2; a++)
        #pragma unroll
        for (int b = 0; b < 8; b++)
            #pragma unroll
            for (int c = 0; c < 4; c++) acc[a][b][c] = 0.f;

    load_stage(0, 0); cp_commit();

    const int NK = II / BK;   // 32
    for (int kt = 0; kt < NK; kt++) {
        const int buf = kt & 1;
        if (kt + 1 < NK) {
            load_stage((kt + 1) * BK, buf ^ 1); cp_commit();
            asm volatile("cp.async.wait_group 1;\n");
        } else {
            asm volatile("cp.async.wait_group 0;\n");
        }
        __syncthreads();

        #pragma unroll
        for (int kk = 0; kk < BK; kk += 8) {
            const int c0 = (((kk >> 2)    ) ^ grp) << 2;
            const int c1 = (((kk >> 2) + 1) ^ grp) << 2;
            uint32_t a[2][4];
            #pragma unroll
            for (int mi = 0; mi < 2; mi++) {
                const int r0 = wm + mi * 16 + grp, r1 = r0 + 8;
                a[mi][0] = __float_as_uint(As[buf][r0][c0 + tg]);
                a[mi][1] = __float_as_uint(As[buf][r1][c0 + tg]);
                a[mi][2] = __float_as_uint(As[buf][r0][c1 + tg]);
                a[mi][3] = __float_as_uint(As[buf][r1][c1 + tg]);
            }
            #pragma unroll
            for (int ni = 0; ni < 8; ni++) {
                const int col = wn + ni * 8 + grp;
                const uint32_t b0 = tf32r(Bs[buf][col][c0 + tg]);
                const uint32_t b1 = tf32r(Bs[buf][col][c1 + tg]);
                #pragma unroll
                for (int mi = 0; mi < 2; mi++)
                    mma_tf32(acc[mi][ni], a[mi], b0, b1);
            }
        }
        __syncthreads();
    }

    // epilogue: per-pair partial rows (deterministic, no atomics)
    #pragma unroll
    for (int mi = 0; mi < 2; mi++) {
        #pragma unroll
        for (int h2 = 0; h2 < 2; h2++) {
            const int rloc = wm + mi * 16 + grp + h2 * 8;
            const int slot = mt * BM + rloc;
            if (slot >= ne) continue;
            float* orow = g_o[g_prow[e][slot]];
            #pragma unroll
            for (int ni = 0; ni < 8; ni++) {
                *reinterpret_cast<float2*>(orow + nt * BN2 + wn + ni * 8 + tg * 2) =
                    make_float2(acc[mi][ni][h2 * 2 + 0], acc[mi][ni][h2 * 2 + 1]);
            }
        }
    }
}

// ---------------- kernel 4: combine the two pairs of each token --------------
__global__ __launch_bounds__(256)
void combine_kernel(float* __restrict__ out) {
    const int i = blockIdx.x * 256 + threadIdx.x;   // over TT*HH/4 float4s
    const int t = i >> 9;                           // HH/4 = 512
    const int c = i & 511;
    const float4 a = reinterpret_cast<const float4*>(&g_o[2 * t][0])[c];
    const float4 b = reinterpret_cast<const float4*>(&g_o[2 * t + 1][0])[c];
    reinterpret_cast<float4*>(out)[i] =
        make_float4(a.x + b.x, a.y + b.y, a.z + b.z, a.w + b.w);
}

// ---------------- launch -----------------------------------------------------
extern "C" void kernel_launch(void* const* d_in, const int* in_sizes, int n_in,
                              void* d_out, int out_size) {
    const float* x  = (const float*)d_in[0];   // [T, H]
    const float* gw = (const float*)d_in[1];   // [E, H] router
    const float* wg = (const float*)d_in[2];   // [E, I, H] gate_proj
    const float* wu = (const float*)d_in[3];   // [E, I, H] up_proj
    const float* wd = (const float*)d_in[4];   // [E, H, I] down_proj
    float* out = (float*)d_out;                // [T, H]

    zero_cnt_kernel<<<1, 32>>>();
    router_kernel<<<TT / RT, 128>>>(x, gw);
    moe_g1_kernel<<<dim3(II / BN1, EE * 16), 128>>>(wg, wu);
    moe_g2_kernel<<<dim3(HH / BN2, EE * 16), 128>>>(wd);
    combine_kernel<<<(TT * HH / 4) / 256, 256>>>(out);
}